// round 15
// baseline (speedup 1.0000x reference)
#include <cuda_runtime.h>
#include <cuda_fp16.h>
#include <math.h>
#include <stdint.h>

#define BT    16384
#define DDIM  4096
#define NCOLS 320
#define EPSF  1.1920929e-07f
#define BSCALE 64.0f
#define INVBS  0.015625f

#define BM  128
#define BK  64
#define KIT (DDIM / BK)   // 64

// smem per stage (128B rows): A 128 rows x 128B = 16KB ; B 320 rows x 128B = 40KB
#define SA   0
#define SB   16384
#define STG  57344
#define NST  3
#define SMEM_TOTAL (NST * STG)   // 172032

__device__ float g_h[(size_t)BT * NCOLS];
__device__ __half g_bh[(size_t)NCOLS * DDIM];

__device__ __forceinline__ uint32_t smem_u32(const void* p) {
    uint32_t a;
    asm("{ .reg .u64 t; cvta.to.shared.u64 t, %1; cvt.u32.u64 %0, t; }" : "=r"(a) : "l"(p));
    return a;
}
// 128B-row swizzle: 16B unit u (0..7) XOR (row mod 8)
__device__ __forceinline__ uint32_t swz128(int row, int u) {
    return (uint32_t)(row * 128 + ((u ^ (row & 7)) << 4));
}
__device__ __forceinline__ void st4(uint32_t a, uint32_t x, uint32_t y, uint32_t z, uint32_t w) {
    asm volatile("st.shared.v4.b32 [%0], {%1,%2,%3,%4};" :: "r"(a), "r"(x), "r"(y), "r"(z), "r"(w));
}
__device__ __forceinline__ void cpa16(uint32_t dst, const void* src) {
    asm volatile("cp.async.cg.shared.global [%0], [%1], 16;"
        :: "r"(dst), "l"((size_t)__cvta_generic_to_global(src)) : "memory");
}
#define CP_COMMIT() asm volatile("cp.async.commit_group;" ::: "memory")
#define CP_WAIT2()  asm volatile("cp.async.wait_group 2;" ::: "memory")

#define LDM4(r, a) \
    asm volatile("ldmatrix.sync.aligned.m8n8.x4.shared.b16 {%0,%1,%2,%3}, [%4];" \
        : "=r"((r)[0]), "=r"((r)[1]), "=r"((r)[2]), "=r"((r)[3]) : "r"(a))

#define MMA(c, a, b) \
    asm volatile("mma.sync.aligned.m16n8k16.row.col.f32.f16.f16.f32 " \
        "{%0,%1,%2,%3},{%4,%5,%6,%7},{%8,%9},{%0,%1,%2,%3};" \
        : "+f"((c)[0]), "+f"((c)[1]), "+f"((c)[2]), "+f"((c)[3]) \
        : "r"((a)[0]), "r"((a)[1]), "r"((a)[2]), "r"((a)[3]), "r"((b)[0]), "r"((b)[1]))

// ---- kernel 1: pack selected W columns (x64) into fp16 ----
__global__ void pack_b_kernel(const float* __restrict__ dw1, const float* __restrict__ dd) {
    int idx = blockIdx.x * blockDim.x + threadIdx.x;
    if (idx >= NCOLS * DDIM) return;
    int n = idx / DDIM, k = idx % DDIM;
    float v;
    if (n < 128)      v = dw1[k * 512 + n];
    else if (n < 256) v = dw1[k * 512 + 256 + (n - 128)];
    else if (n < 288) v = dd[k * 128 + (n - 256)];
    else              v = dd[k * 128 + 64 + (n - 288)];
    g_bh[idx] = __float2half_rn(v * BSCALE);
}

// ---- kernel 2: fp16 HMMA GEMM, BK=64, 3-stage ring, one barrier/iter ----
__global__ void __launch_bounds__(512, 1) gemm_hmma(const float* __restrict__ Q) {
    extern __shared__ __align__(1024) unsigned char sm[];
    const uint32_t sb = smem_u32(sm);
    const int tid = threadIdx.x, lane = tid & 31, wid = tid >> 5;
    const int wm = wid & 3, wn = wid >> 2;
    const int m0 = blockIdx.x * BM;

    // A convert mapping: 4 threads/row, each covers 16 consecutive k
    const int arow = tid >> 2, au = tid & 3;
    const float* aptr = Q + (size_t)(m0 + arow) * DDIM + au * 16;
    const uint32_t a_dst0 = SA + swz128(arow, 2 * au);
    const uint32_t a_dst1 = SA + swz128(arow, 2 * au + 1);

    // B cp.async: 2560 units over 512 threads = 5 each; constant strides
    const int brow0 = tid >> 3, bu = tid & 7;
    const __half* bsrc0 = g_bh + (size_t)brow0 * DDIM + bu * 8;
    const uint32_t bdst0 = SB + swz128(brow0, bu);

    // ldmatrix bases (row-group strides are multiples of 8 -> phase = lane&7)
    const int la = lane >> 4;          // A k16-pair select
    const int lb = (lane >> 3) & 1;    // B k16-pair select
    const int rsw = lane & 7;
    const uint32_t a_r = (uint32_t)((wm * 32 + (lane & 15)) * 128);
    const uint32_t b_r = (uint32_t)((wn * 80 + ((lane >> 4) & 1) * 8 + (lane & 7)) * 128);

    float4 ra0, ra1, ra2, ra3;
    float acc[2][10][4];
#pragma unroll
    for (int i = 0; i < 2; i++)
#pragma unroll
        for (int j = 0; j < 10; j++)
#pragma unroll
            for (int v = 0; v < 4; v++) acc[i][j][v] = 0.0f;

#define LDGA(i) do { const float4* _p = (const float4*)(aptr + (size_t)(i) * BK); \
    ra0 = __ldg(_p); ra1 = __ldg(_p + 1); ra2 = __ldg(_p + 2); ra3 = __ldg(_p + 3); } while (0)

#define STSA(stg) do { \
    __half2 c0 = __floats2half2_rn(ra0.x, ra0.y); \
    __half2 c1 = __floats2half2_rn(ra0.z, ra0.w); \
    __half2 c2 = __floats2half2_rn(ra1.x, ra1.y); \
    __half2 c3 = __floats2half2_rn(ra1.z, ra1.w); \
    st4((stg) + a_dst0, *(uint32_t*)&c0, *(uint32_t*)&c1, *(uint32_t*)&c2, *(uint32_t*)&c3); \
    c0 = __floats2half2_rn(ra2.x, ra2.y); \
    c1 = __floats2half2_rn(ra2.z, ra2.w); \
    c2 = __floats2half2_rn(ra3.x, ra3.y); \
    c3 = __floats2half2_rn(ra3.z, ra3.w); \
    st4((stg) + a_dst1, *(uint32_t*)&c0, *(uint32_t*)&c1, *(uint32_t*)&c2, *(uint32_t*)&c3); } while (0)

#define CPB(i, stg) do { \
    _Pragma("unroll") \
    for (int _j = 0; _j < 5; _j++) \
        cpa16((stg) + bdst0 + _j * 8192, bsrc0 + (size_t)_j * 64 * DDIM + (size_t)(i) * BK); } while (0)

    // prologue: B groups g0,g1 in flight; A(0) stored; A(1) in regs
    LDGA(0);
    CPB(0, sb); CP_COMMIT();
    CPB(1, sb + STG); CP_COMMIT();
    STSA(sb);
    LDGA(1);
    __syncthreads();

    for (int i = 0; i < KIT; i++) {
        const uint32_t scur = sb + (i % 3) * STG;
        if (i + 2 < KIT) CPB(i + 2, sb + ((i + 2) % 3) * STG);
        CP_COMMIT();
        CP_WAIT2();   // group i complete

#pragma unroll
        for (int kk = 0; kk < 4; kk++) {
            uint32_t ah[2][4];
#pragma unroll
            for (int t = 0; t < 2; t++) {
                uint32_t auo = (uint32_t)((((kk << 1) + la) ^ rsw) << 4);
                LDM4(ah[t], scur + SA + a_r + t * 2048 + auo);
            }
#pragma unroll
            for (int t5 = 0; t5 < 5; t5++) {
                uint32_t buo = (uint32_t)((((kk << 1) + lb) ^ rsw) << 4);
                uint32_t bh4[4];
                LDM4(bh4, scur + SB + b_r + t5 * 2048 + buo);
#pragma unroll
                for (int mt = 0; mt < 2; mt++)
#pragma unroll
                    for (int s = 0; s < 2; s++)
                        MMA(acc[mt][t5 * 2 + s], ah[mt], &bh4[s * 2]);
            }
        }

        if (i + 1 < KIT) STSA(sb + ((i + 1) % 3) * STG);
        if (i + 2 < KIT) LDGA(i + 2);
        __syncthreads();
    }

    // store H (scaled by BSCALE)
#pragma unroll
    for (int mt = 0; mt < 2; mt++) {
        int row = m0 + wm * 32 + mt * 16 + (lane >> 2);
#pragma unroll
        for (int nt = 0; nt < 10; nt++) {
            int col = wn * 80 + nt * 8 + (lane & 3) * 2;
            *(float2*)&g_h[(size_t)row * NCOLS + col] =
                make_float2(acc[mt][nt][0], acc[mt][nt][1]);
            *(float2*)&g_h[(size_t)(row + 8) * NCOLS + col] =
                make_float2(acc[mt][nt][2], acc[mt][nt][3]);
        }
    }
}

// ---- kernel 3: per-token epilogue (f32x2 packed FMA) ----
__global__ __launch_bounds__(256) void epilogue_kernel(const float* __restrict__ qkw,
                                                       const float* __restrict__ norm_scale,
                                                       float* __restrict__ out) {
    const int lane = threadIdx.x & 31, w = threadIdx.x >> 5;
    const int tok = blockIdx.x * 8 + w;
    if (tok >= BT) return;
    const float* h = g_h + (size_t)tok * NCOLS;
    float* o = out + (size_t)tok * NCOLS;
    const float scale = norm_scale[0];
    const int ii = lane >> 3, m4 = (lane & 7) * 4;

    __shared__ float hg[8][256];
#pragma unroll
    for (int p = 0; p < 8; p++) {
        float x = h[lane + p * 32] * INVBS;
        hg[w][lane + p * 32] = 0.5f * x * (1.0f + erff(x * 0.70710678118654752f));
    }
    o[128 + lane] = tanhf(h[256 + lane] * INVBS);
    o[288 + lane] = tanhf(h[288 + lane] * INVBS);
    __syncwarp();

#pragma unroll
    for (int cc = 0; cc < 2; cc++) {
        const float* qc = qkw + (size_t)(cc * 2) * 16384 + ii * 32 + m4;
        const float* hh = &hg[w][cc * 128];
        uint64_t acc01 = 0ull, acc23 = 0ull;
#pragma unroll 4
        for (int k = 0; k < 128; k++) {
            float hk = hh[k];
            uint64_t hk2;
            asm("mov.b64 %0, {%1, %1};" : "=l"(hk2) : "f"(hk));
            ulonglong2 wv = *(const ulonglong2*)(qc + (size_t)k * 128);
            asm("fma.rn.f32x2 %0, %1, %2, %0;" : "+l"(acc01) : "l"(hk2), "l"(wv.x));
            asm("fma.rn.f32x2 %0, %1, %2, %0;" : "+l"(acc23) : "l"(hk2), "l"(wv.y));
        }
        float a0, a1, a2, a3;
        asm("mov.b64 {%0, %1}, %2;" : "=f"(a0), "=f"(a1) : "l"(acc01));
        asm("mov.b64 {%0, %1}, %2;" : "=f"(a2), "=f"(a3) : "l"(acc23));
        float ss = a0 * a0 + a1 * a1 + a2 * a2 + a3 * a3;
#pragma unroll
        for (int m = 1; m < 8; m <<= 1) ss += __shfl_xor_sync(0xFFFFFFFFu, ss, m);
        float r = rsqrtf(ss * (1.0f / 32.0f) + EPSF);
        if (ii >= 2) r *= scale;
        *(float4*)&o[cc * 160 + ii * 32 + m4] = make_float4(a0 * r, a1 * r, a2 * r, a3 * r);
    }
}

extern "C" void kernel_launch(void* const* d_in, const int* in_sizes, int n_in,
                              void* d_out, int out_size) {
    const float* q   = (const float*)d_in[0];
    const float* dw1 = (const float*)d_in[1];
    const float* qkw = (const float*)d_in[2];
    const float* dd  = (const float*)d_in[3];
    const float* nsc = (const float*)d_in[4];
    float* out = (float*)d_out;

    cudaFuncSetAttribute(gemm_hmma, cudaFuncAttributeMaxDynamicSharedMemorySize, SMEM_TOTAL);
    pack_b_kernel<<<(NCOLS * DDIM + 255) / 256, 256>>>(dw1, dd);
    gemm_hmma<<<BT / BM, 512, SMEM_TOTAL>>>(q);
    epilogue_kernel<<<BT / 8, 256>>>(qkw, nsc, out);
}

// round 16
// speedup vs baseline: 1.0160x; 1.0160x over previous
#include <cuda_runtime.h>
#include <cuda_fp16.h>
#include <math.h>
#include <stdint.h>

#define BT    16384
#define DDIM  4096
#define NCOLS 320
#define EPSF  1.1920929e-07f
#define BSCALE 64.0f
#define INVBS  0.015625f

#define BM  128
#define BK  32
#define KIT (DDIM / BK)

// smem per stage: A 128 rows x 64B (fp16) = 8KB ; B 320 rows x 64B = 20KB
#define SA   0
#define SB   8192
#define STG  28672
#define NST  3
#define SMEM_TOTAL (NST * STG)   // 86016

__device__ float g_h[(size_t)BT * NCOLS];
__device__ __half g_bh[(size_t)NCOLS * DDIM];

__device__ __forceinline__ uint32_t smem_u32(const void* p) {
    uint32_t a;
    asm("{ .reg .u64 t; cvta.to.shared.u64 t, %1; cvt.u32.u64 %0, t; }" : "=r"(a) : "l"(p));
    return a;
}
__device__ __forceinline__ uint32_t swz(int row, int u) {
    return (uint32_t)(row * 64 + ((u ^ ((row >> 1) & 3)) << 4));
}
__device__ __forceinline__ void st4(uint32_t a, uint32_t x, uint32_t y, uint32_t z, uint32_t w) {
    asm volatile("st.shared.v4.b32 [%0], {%1,%2,%3,%4};" :: "r"(a), "r"(x), "r"(y), "r"(z), "r"(w));
}
__device__ __forceinline__ void cpa16(uint32_t dst, const void* src) {
    asm volatile("cp.async.cg.shared.global [%0], [%1], 16;"
        :: "r"(dst), "l"((size_t)__cvta_generic_to_global(src)) : "memory");
}
#define CP_COMMIT() asm volatile("cp.async.commit_group;" ::: "memory")
#define CP_WAIT2()  asm volatile("cp.async.wait_group 2;" ::: "memory")

#define LDM4(r, a) \
    asm volatile("ldmatrix.sync.aligned.m8n8.x4.shared.b16 {%0,%1,%2,%3}, [%4];" \
        : "=r"((r)[0]), "=r"((r)[1]), "=r"((r)[2]), "=r"((r)[3]) : "r"(a))

#define MMA(c, a, b) \
    asm volatile("mma.sync.aligned.m16n8k16.row.col.f32.f16.f16.f32 " \
        "{%0,%1,%2,%3},{%4,%5,%6,%7},{%8,%9},{%0,%1,%2,%3};" \
        : "+f"((c)[0]), "+f"((c)[1]), "+f"((c)[2]), "+f"((c)[3]) \
        : "r"((a)[0]), "r"((a)[1]), "r"((a)[2]), "r"((a)[3]), "r"((b)[0]), "r"((b)[1]))

// ---- kernel 1: pack selected W columns (x64) into fp16 ----
__global__ void pack_b_kernel(const float* __restrict__ dw1, const float* __restrict__ dd) {
    int idx = blockIdx.x * blockDim.x + threadIdx.x;
    if (idx >= NCOLS * DDIM) return;
    int n = idx / DDIM, k = idx % DDIM;
    float v;
    if (n < 128)      v = dw1[k * 512 + n];
    else if (n < 256) v = dw1[k * 512 + 256 + (n - 128)];
    else if (n < 288) v = dd[k * 128 + (n - 256)];
    else              v = dd[k * 128 + 64 + (n - 288)];
    g_bh[idx] = __float2half_rn(v * BSCALE);
}

// ---- kernel 2: fp16 HMMA GEMM, 3-stage ring, ONE barrier/iter (R14 best) ----
__global__ void __launch_bounds__(512, 1) gemm_hmma(const float* __restrict__ Q) {
    extern __shared__ __align__(1024) unsigned char sm[];
    const uint32_t sb = smem_u32(sm);
    const int tid = threadIdx.x, lane = tid & 31, wid = tid >> 5;
    const int wm = wid & 3, wn = wid >> 2;
    const int m0 = blockIdx.x * BM;

    const int arow = tid >> 2, au = tid & 3;
    const float* aptr = Q + (size_t)(m0 + arow) * DDIM + au * 8;
    const uint32_t a_dst = SA + swz(arow, au);

    const __half* bsrc[3];
    uint32_t bdst[3];
    const bool b3 = (tid < 256);
#pragma unroll
    for (int j = 0; j < 3; j++) {
        int idx = tid + j * 512;
        int row = (j < 2 || b3) ? (idx >> 2) : 0;
        int u = idx & 3;
        bsrc[j] = g_bh + (size_t)row * DDIM + u * 8;
        bdst[j] = SB + swz(row, u);
    }

    const int la = lane >> 4;
    const int lb = (lane >> 3) & 1;
    uint32_t a_r64[2]; int a_rsw[2];
#pragma unroll
    for (int t = 0; t < 2; t++) {
        int ra = wm * 32 + (lane & 15) + t * 16;
        a_r64[t] = ra * 64; a_rsw[t] = (ra >> 1) & 3;
    }
    uint32_t b_r64[5]; int b_rsw[5];
#pragma unroll
    for (int t = 0; t < 5; t++) {
        int rb = wn * 80 + t * 16 + ((lane >> 4) & 1) * 8 + (lane & 7);
        b_r64[t] = rb * 64; b_rsw[t] = (rb >> 1) & 3;
    }

    float4 ra0, ra1;
    float acc[2][10][4];
#pragma unroll
    for (int i = 0; i < 2; i++)
#pragma unroll
        for (int j = 0; j < 10; j++)
#pragma unroll
            for (int v = 0; v < 4; v++) acc[i][j][v] = 0.0f;

#define LDGA(i) do { const float4* _p = (const float4*)(aptr + (size_t)(i) * BK); \
    ra0 = __ldg(_p); ra1 = __ldg(_p + 1); } while (0)

#define STSA(stg) do { \
    __half2 c0 = __floats2half2_rn(ra0.x, ra0.y); \
    __half2 c1 = __floats2half2_rn(ra0.z, ra0.w); \
    __half2 c2 = __floats2half2_rn(ra1.x, ra1.y); \
    __half2 c3 = __floats2half2_rn(ra1.z, ra1.w); \
    st4((stg) + a_dst, *(uint32_t*)&c0, *(uint32_t*)&c1, *(uint32_t*)&c2, *(uint32_t*)&c3); } while (0)

#define CPB(i, stg) do { \
    cpa16((stg) + bdst[0], bsrc[0] + (size_t)(i) * BK); \
    cpa16((stg) + bdst[1], bsrc[1] + (size_t)(i) * BK); \
    if (b3) cpa16((stg) + bdst[2], bsrc[2] + (size_t)(i) * BK); } while (0)

    LDGA(0);
    CPB(0, sb); CP_COMMIT();
    CPB(1, sb + STG); CP_COMMIT();
    STSA(sb);
    LDGA(1);
    __syncthreads();

    for (int i = 0; i < KIT; i++) {
        const uint32_t scur = sb + (i % 3) * STG;
        if (i + 2 < KIT) CPB(i + 2, sb + ((i + 2) % 3) * STG);
        CP_COMMIT();
        CP_WAIT2();

#pragma unroll
        for (int kk = 0; kk < 2; kk++) {
            uint32_t ah[2][4];
#pragma unroll
            for (int t = 0; t < 2; t++) {
                uint32_t auo = (uint32_t)((((kk << 1) + la) ^ a_rsw[t]) << 4);
                LDM4(ah[t], scur + SA + a_r64[t] + auo);
            }
#pragma unroll
            for (int t5 = 0; t5 < 5; t5++) {
                uint32_t buo = (uint32_t)((((kk << 1) + lb) ^ b_rsw[t5]) << 4);
                uint32_t bh4[4];
                LDM4(bh4, scur + SB + b_r64[t5] + buo);
#pragma unroll
                for (int mt = 0; mt < 2; mt++)
#pragma unroll
                    for (int s = 0; s < 2; s++)
                        MMA(acc[mt][t5 * 2 + s], ah[mt], &bh4[s * 2]);
            }
        }

        if (i + 1 < KIT) STSA(sb + ((i + 1) % 3) * STG);
        if (i + 2 < KIT) LDGA(i + 2);
        __syncthreads();
    }

#pragma unroll
    for (int mt = 0; mt < 2; mt++) {
        int row = m0 + wm * 32 + mt * 16 + (lane >> 2);
#pragma unroll
        for (int nt = 0; nt < 10; nt++) {
            int col = wn * 80 + nt * 8 + (lane & 3) * 2;
            *(float2*)&g_h[(size_t)row * NCOLS + col] =
                make_float2(acc[mt][nt][0], acc[mt][nt][1]);
            *(float2*)&g_h[(size_t)(row + 8) * NCOLS + col] =
                make_float2(acc[mt][nt][2], acc[mt][nt][3]);
        }
    }
}

// ---- kernel 3: epilogue, 4 tokens/warp, transposed H staging ----
#define HT_STRIDE 36   // 36*4=144 B row pitch: 16B-aligned for LDS.128
__global__ __launch_bounds__(256) void epilogue_kernel(const float* __restrict__ qkw,
                                                       const float* __restrict__ norm_scale,
                                                       float* __restrict__ out) {
    const int tid = threadIdx.x, lane = tid & 31, w = tid >> 5;
    const int tok0 = blockIdx.x * 32;
    const float scale = norm_scale[0];

    __shared__ float hgT[256 * HT_STRIDE];   // [col][token], 36.9 KB

    // gelu: row p of 32, coalesced g_h read, transposed STS
#pragma unroll 4
    for (int p = 0; p < 32; p++) {
        float x = g_h[(size_t)(tok0 + p) * NCOLS + tid] * INVBS;
        hgT[tid * HT_STRIDE + p] = 0.5f * x * (1.0f + erff(x * 0.70710678118654752f));
    }
    // dd path: warp handles its 4 tokens
#pragma unroll
    for (int t = 0; t < 4; t++) {
        const size_t tok = tok0 + w * 4 + t;
        out[tok * NCOLS + 128 + lane] = tanhf(g_h[tok * NCOLS + 256 + lane] * INVBS);
        out[tok * NCOLS + 288 + lane] = tanhf(g_h[tok * NCOLS + 288 + lane] * INVBS);
    }
    __syncthreads();

    const int ii = lane >> 3, m4 = (lane & 7) * 4;
#pragma unroll
    for (int cc = 0; cc < 2; cc++) {
        const float* qc = qkw + (size_t)(cc * 2) * 16384 + ii * 32 + m4;
        const float* hbase = hgT + (cc * 128) * HT_STRIDE + w * 4;
        uint64_t a01[4], a23[4];
#pragma unroll
        for (int t = 0; t < 4; t++) { a01[t] = 0ull; a23[t] = 0ull; }
#pragma unroll 4
        for (int k = 0; k < 128; k++) {
            ulonglong2 wv = *(const ulonglong2*)(qc + (size_t)k * 128);
            float4 hk4 = *(const float4*)(hbase + k * HT_STRIDE);
            uint64_t h2;
            asm("mov.b64 %0, {%1, %1};" : "=l"(h2) : "f"(hk4.x));
            asm("fma.rn.f32x2 %0, %1, %2, %0;" : "+l"(a01[0]) : "l"(h2), "l"(wv.x));
            asm("fma.rn.f32x2 %0, %1, %2, %0;" : "+l"(a23[0]) : "l"(h2), "l"(wv.y));
            asm("mov.b64 %0, {%1, %1};" : "=l"(h2) : "f"(hk4.y));
            asm("fma.rn.f32x2 %0, %1, %2, %0;" : "+l"(a01[1]) : "l"(h2), "l"(wv.x));
            asm("fma.rn.f32x2 %0, %1, %2, %0;" : "+l"(a23[1]) : "l"(h2), "l"(wv.y));
            asm("mov.b64 %0, {%1, %1};" : "=l"(h2) : "f"(hk4.z));
            asm("fma.rn.f32x2 %0, %1, %2, %0;" : "+l"(a01[2]) : "l"(h2), "l"(wv.x));
            asm("fma.rn.f32x2 %0, %1, %2, %0;" : "+l"(a23[2]) : "l"(h2), "l"(wv.y));
            asm("mov.b64 %0, {%1, %1};" : "=l"(h2) : "f"(hk4.w));
            asm("fma.rn.f32x2 %0, %1, %2, %0;" : "+l"(a01[3]) : "l"(h2), "l"(wv.x));
            asm("fma.rn.f32x2 %0, %1, %2, %0;" : "+l"(a23[3]) : "l"(h2), "l"(wv.y));
        }
#pragma unroll
        for (int t = 0; t < 4; t++) {
            float a0, a1, a2, a3;
            asm("mov.b64 {%0, %1}, %2;" : "=f"(a0), "=f"(a1) : "l"(a01[t]));
            asm("mov.b64 {%0, %1}, %2;" : "=f"(a2), "=f"(a3) : "l"(a23[t]));
            float ss = a0 * a0 + a1 * a1 + a2 * a2 + a3 * a3;
#pragma unroll
            for (int m = 1; m < 8; m <<= 1) ss += __shfl_xor_sync(0xFFFFFFFFu, ss, m);
            float r = rsqrtf(ss * (1.0f / 32.0f) + EPSF);
            if (ii >= 2) r *= scale;
            float* o = out + (size_t)(tok0 + w * 4 + t) * NCOLS + cc * 160 + ii * 32 + m4;
            *(float4*)o = make_float4(a0 * r, a1 * r, a2 * r, a3 * r);
        }
    }
}

extern "C" void kernel_launch(void* const* d_in, const int* in_sizes, int n_in,
                              void* d_out, int out_size) {
    const float* q   = (const float*)d_in[0];
    const float* dw1 = (const float*)d_in[1];
    const float* qkw = (const float*)d_in[2];
    const float* dd  = (const float*)d_in[3];
    const float* nsc = (const float*)d_in[4];
    float* out = (float*)d_out;

    cudaFuncSetAttribute(gemm_hmma, cudaFuncAttributeMaxDynamicSharedMemorySize, SMEM_TOTAL);
    pack_b_kernel<<<(NCOLS * DDIM + 255) / 256, 256>>>(dw1, dd);
    gemm_hmma<<<BT / BM, 512, SMEM_TOTAL>>>(q);
    epilogue_kernel<<<BT / 32, 256>>>(qkw, nsc, out);
}

// round 17
// speedup vs baseline: 1.1279x; 1.1101x over previous
#include <cuda_runtime.h>
#include <cuda_fp16.h>
#include <math.h>
#include <stdint.h>

#define BT    16384
#define DDIM  4096
#define NCOLS 320
#define EPSF  1.1920929e-07f
#define BSCALE 64.0f
#define INVBS  0.015625f

#define BM  128
#define BK  32
#define KIT (DDIM / BK)

// smem per stage: A 128 rows x 64B (fp16) = 8KB ; B 320 rows x 64B = 20KB
#define SA   0
#define SB   8192
#define STG  28672
#define NST  3
#define SMEM_TOTAL (NST * STG)   // 86016

__device__ float g_h[(size_t)BT * NCOLS];
__device__ __half g_bh[(size_t)NCOLS * DDIM];

__device__ __forceinline__ uint32_t smem_u32(const void* p) {
    uint32_t a;
    asm("{ .reg .u64 t; cvta.to.shared.u64 t, %1; cvt.u32.u64 %0, t; }" : "=r"(a) : "l"(p));
    return a;
}
__device__ __forceinline__ uint32_t swz(int row, int u) {
    return (uint32_t)(row * 64 + ((u ^ ((row >> 1) & 3)) << 4));
}
__device__ __forceinline__ void st4(uint32_t a, uint32_t x, uint32_t y, uint32_t z, uint32_t w) {
    asm volatile("st.shared.v4.b32 [%0], {%1,%2,%3,%4};" :: "r"(a), "r"(x), "r"(y), "r"(z), "r"(w));
}
__device__ __forceinline__ void cpa16(uint32_t dst, const void* src) {
    asm volatile("cp.async.cg.shared.global [%0], [%1], 16;"
        :: "r"(dst), "l"((size_t)__cvta_generic_to_global(src)) : "memory");
}
#define CP_COMMIT() asm volatile("cp.async.commit_group;" ::: "memory")
#define CP_WAIT2()  asm volatile("cp.async.wait_group 2;" ::: "memory")

#define LDM4(r, a) \
    asm volatile("ldmatrix.sync.aligned.m8n8.x4.shared.b16 {%0,%1,%2,%3}, [%4];" \
        : "=r"((r)[0]), "=r"((r)[1]), "=r"((r)[2]), "=r"((r)[3]) : "r"(a))

#define MMA(c, a, b) \
    asm volatile("mma.sync.aligned.m16n8k16.row.col.f32.f16.f16.f32 " \
        "{%0,%1,%2,%3},{%4,%5,%6,%7},{%8,%9},{%0,%1,%2,%3};" \
        : "+f"((c)[0]), "+f"((c)[1]), "+f"((c)[2]), "+f"((c)[3]) \
        : "r"((a)[0]), "r"((a)[1]), "r"((a)[2]), "r"((a)[3]), "r"((b)[0]), "r"((b)[1]))

// ---- kernel 1: pack selected W columns (x64) into fp16 ----
__global__ void pack_b_kernel(const float* __restrict__ dw1, const float* __restrict__ dd) {
    int idx = blockIdx.x * blockDim.x + threadIdx.x;
    if (idx >= NCOLS * DDIM) return;
    int n = idx / DDIM, k = idx % DDIM;
    float v;
    if (n < 128)      v = dw1[k * 512 + n];
    else if (n < 256) v = dw1[k * 512 + 256 + (n - 128)];
    else if (n < 288) v = dd[k * 128 + (n - 256)];
    else              v = dd[k * 128 + 64 + (n - 288)];
    g_bh[idx] = __float2half_rn(v * BSCALE);
}

// ---- kernel 2: fp16 HMMA GEMM, 3-stage ring, ONE barrier/iter (R14 best) ----
__global__ void __launch_bounds__(512, 1) gemm_hmma(const float* __restrict__ Q) {
    extern __shared__ __align__(1024) unsigned char sm[];
    const uint32_t sb = smem_u32(sm);
    const int tid = threadIdx.x, lane = tid & 31, wid = tid >> 5;
    const int wm = wid & 3, wn = wid >> 2;
    const int m0 = blockIdx.x * BM;

    const int arow = tid >> 2, au = tid & 3;
    const float* aptr = Q + (size_t)(m0 + arow) * DDIM + au * 8;
    const uint32_t a_dst = SA + swz(arow, au);

    const __half* bsrc[3];
    uint32_t bdst[3];
    const bool b3 = (tid < 256);
#pragma unroll
    for (int j = 0; j < 3; j++) {
        int idx = tid + j * 512;
        int row = (j < 2 || b3) ? (idx >> 2) : 0;
        int u = idx & 3;
        bsrc[j] = g_bh + (size_t)row * DDIM + u * 8;
        bdst[j] = SB + swz(row, u);
    }

    const int la = lane >> 4;
    const int lb = (lane >> 3) & 1;
    uint32_t a_r64[2]; int a_rsw[2];
#pragma unroll
    for (int t = 0; t < 2; t++) {
        int ra = wm * 32 + (lane & 15) + t * 16;
        a_r64[t] = ra * 64; a_rsw[t] = (ra >> 1) & 3;
    }
    uint32_t b_r64[5]; int b_rsw[5];
#pragma unroll
    for (int t = 0; t < 5; t++) {
        int rb = wn * 80 + t * 16 + ((lane >> 4) & 1) * 8 + (lane & 7);
        b_r64[t] = rb * 64; b_rsw[t] = (rb >> 1) & 3;
    }

    float4 ra0, ra1;
    float acc[2][10][4];
#pragma unroll
    for (int i = 0; i < 2; i++)
#pragma unroll
        for (int j = 0; j < 10; j++)
#pragma unroll
            for (int v = 0; v < 4; v++) acc[i][j][v] = 0.0f;

#define LDGA(i) do { const float4* _p = (const float4*)(aptr + (size_t)(i) * BK); \
    ra0 = __ldg(_p); ra1 = __ldg(_p + 1); } while (0)

#define STSA(stg) do { \
    __half2 c0 = __floats2half2_rn(ra0.x, ra0.y); \
    __half2 c1 = __floats2half2_rn(ra0.z, ra0.w); \
    __half2 c2 = __floats2half2_rn(ra1.x, ra1.y); \
    __half2 c3 = __floats2half2_rn(ra1.z, ra1.w); \
    st4((stg) + a_dst, *(uint32_t*)&c0, *(uint32_t*)&c1, *(uint32_t*)&c2, *(uint32_t*)&c3); } while (0)

#define CPB(i, stg) do { \
    cpa16((stg) + bdst[0], bsrc[0] + (size_t)(i) * BK); \
    cpa16((stg) + bdst[1], bsrc[1] + (size_t)(i) * BK); \
    if (b3) cpa16((stg) + bdst[2], bsrc[2] + (size_t)(i) * BK); } while (0)

    LDGA(0);
    CPB(0, sb); CP_COMMIT();
    CPB(1, sb + STG); CP_COMMIT();
    STSA(sb);
    LDGA(1);
    __syncthreads();

    for (int i = 0; i < KIT; i++) {
        const uint32_t scur = sb + (i % 3) * STG;
        if (i + 2 < KIT) CPB(i + 2, sb + ((i + 2) % 3) * STG);
        CP_COMMIT();
        CP_WAIT2();

#pragma unroll
        for (int kk = 0; kk < 2; kk++) {
            uint32_t ah[2][4];
#pragma unroll
            for (int t = 0; t < 2; t++) {
                uint32_t auo = (uint32_t)((((kk << 1) + la) ^ a_rsw[t]) << 4);
                LDM4(ah[t], scur + SA + a_r64[t] + auo);
            }
#pragma unroll
            for (int t5 = 0; t5 < 5; t5++) {
                uint32_t buo = (uint32_t)((((kk << 1) + lb) ^ b_rsw[t5]) << 4);
                uint32_t bh4[4];
                LDM4(bh4, scur + SB + b_r64[t5] + buo);
#pragma unroll
                for (int mt = 0; mt < 2; mt++)
#pragma unroll
                    for (int s = 0; s < 2; s++)
                        MMA(acc[mt][t5 * 2 + s], ah[mt], &bh4[s * 2]);
            }
        }

        if (i + 1 < KIT) STSA(sb + ((i + 1) % 3) * STG);
        if (i + 2 < KIT) LDGA(i + 2);
        __syncthreads();
    }

#pragma unroll
    for (int mt = 0; mt < 2; mt++) {
        int row = m0 + wm * 32 + mt * 16 + (lane >> 2);
#pragma unroll
        for (int nt = 0; nt < 10; nt++) {
            int col = wn * 80 + nt * 8 + (lane & 3) * 2;
            *(float2*)&g_h[(size_t)row * NCOLS + col] =
                make_float2(acc[mt][nt][0], acc[mt][nt][1]);
            *(float2*)&g_h[(size_t)(row + 8) * NCOLS + col] =
                make_float2(acc[mt][nt][2], acc[mt][nt][3]);
        }
    }
}

// ---- kernel 3: epilogue, 2 tokens per warp (qkw LDG shared), R14 layout ----
__global__ __launch_bounds__(256) void epilogue_kernel(const float* __restrict__ qkw,
                                                       const float* __restrict__ norm_scale,
                                                       float* __restrict__ out) {
    const int lane = threadIdx.x & 31, w = threadIdx.x >> 5;
    const int tok0 = blockIdx.x * 16 + w * 2;   // warp's first token
    const float scale = norm_scale[0];
    const int ii = lane >> 3, m4 = (lane & 7) * 4;

    __shared__ float hg[16][256];

    // gelu staging + dd/tanh for both tokens (same per-token math as R14)
#pragma unroll
    for (int t = 0; t < 2; t++) {
        const float* h = g_h + (size_t)(tok0 + t) * NCOLS;
        float* o = out + (size_t)(tok0 + t) * NCOLS;
#pragma unroll
        for (int p = 0; p < 8; p++) {
            float x = h[lane + p * 32] * INVBS;
            hg[w * 2 + t][lane + p * 32] = 0.5f * x * (1.0f + erff(x * 0.70710678118654752f));
        }
        o[128 + lane] = tanhf(h[256 + lane] * INVBS);
        o[288 + lane] = tanhf(h[288 + lane] * INVBS);
    }
    __syncwarp();

#pragma unroll
    for (int cc = 0; cc < 2; cc++) {
        const float* qc = qkw + (size_t)(cc * 2) * 16384 + ii * 32 + m4;
        const float* hh0 = &hg[w * 2 + 0][cc * 128];
        const float* hh1 = &hg[w * 2 + 1][cc * 128];
        uint64_t a01_0 = 0ull, a23_0 = 0ull, a01_1 = 0ull, a23_1 = 0ull;
#pragma unroll 4
        for (int k = 0; k < 128; k++) {
            ulonglong2 wv = *(const ulonglong2*)(qc + (size_t)k * 128);
            uint64_t h2;
            asm("mov.b64 %0, {%1, %1};" : "=l"(h2) : "f"(hh0[k]));
            asm("fma.rn.f32x2 %0, %1, %2, %0;" : "+l"(a01_0) : "l"(h2), "l"(wv.x));
            asm("fma.rn.f32x2 %0, %1, %2, %0;" : "+l"(a23_0) : "l"(h2), "l"(wv.y));
            asm("mov.b64 %0, {%1, %1};" : "=l"(h2) : "f"(hh1[k]));
            asm("fma.rn.f32x2 %0, %1, %2, %0;" : "+l"(a01_1) : "l"(h2), "l"(wv.x));
            asm("fma.rn.f32x2 %0, %1, %2, %0;" : "+l"(a23_1) : "l"(h2), "l"(wv.y));
        }
#pragma unroll
        for (int t = 0; t < 2; t++) {
            uint64_t a01 = t ? a01_1 : a01_0;
            uint64_t a23 = t ? a23_1 : a23_0;
            float a0, a1, a2, a3;
            asm("mov.b64 {%0, %1}, %2;" : "=f"(a0), "=f"(a1) : "l"(a01));
            asm("mov.b64 {%0, %1}, %2;" : "=f"(a2), "=f"(a3) : "l"(a23));
            float ss = a0 * a0 + a1 * a1 + a2 * a2 + a3 * a3;
#pragma unroll
            for (int m = 1; m < 8; m <<= 1) ss += __shfl_xor_sync(0xFFFFFFFFu, ss, m);
            float r = rsqrtf(ss * (1.0f / 32.0f) + EPSF);
            if (ii >= 2) r *= scale;
            float* o = out + (size_t)(tok0 + t) * NCOLS + cc * 160 + ii * 32 + m4;
            *(float4*)o = make_float4(a0 * r, a1 * r, a2 * r, a3 * r);
        }
    }
}

extern "C" void kernel_launch(void* const* d_in, const int* in_sizes, int n_in,
                              void* d_out, int out_size) {
    const float* q   = (const float*)d_in[0];
    const float* dw1 = (const float*)d_in[1];
    const float* qkw = (const float*)d_in[2];
    const float* dd  = (const float*)d_in[3];
    const float* nsc = (const float*)d_in[4];
    float* out = (float*)d_out;

    cudaFuncSetAttribute(gemm_hmma, cudaFuncAttributeMaxDynamicSharedMemorySize, SMEM_TOTAL);
    pack_b_kernel<<<(NCOLS * DDIM + 255) / 256, 256>>>(dw1, dd);
    gemm_hmma<<<BT / BM, 512, SMEM_TOTAL>>>(q);
    epilogue_kernel<<<BT / 16, 256>>>(qkw, nsc, out);
}